// round 13
// baseline (speedup 1.0000x reference)
#include <cuda_runtime.h>
#include <cuda_fp16.h>
#include <math.h>
#include <stdint.h>

#define NQ 4096
#define NK 32768
#define DIN 1024
#define DQK 512
#define DV 512

// ---------------- scratch (no allocations allowed) ----------------
__device__ __half g_X1h[(size_t)NQ * DIN];
__device__ __half g_Yh[(size_t)NQ * DIN];
__device__ __half g_Uh[(size_t)NQ * DIN];     // U = X1.G + bq.Wk^T (fp16)
__device__ __half g_Wkh[(size_t)DIN * 512];   // Wk split hi   [d2][c]
__device__ __half g_Wkl[(size_t)DIN * 512];   // Wk split lo
__device__ __half g_Wqf[(size_t)DIN * 512];   // fl16(Wq)      [d1][c]
__device__ __half g_WvT[(size_t)512 * DIN];   // Wv^T [n][k] fp16
__device__ __half g_Gh[(size_t)DIN * DIN];    // Gt = Wk.Wq^T, fp16
__device__ float g_c0[NQ];                    // Q[i].bk
__device__ float g_bqWk[DIN];
__device__ float g_wqbk[DIN];
__device__ float g_bqbk[1];
__device__ float g_zb[DIN];                   // zero bias (never written)
__device__ int   g_cnt[NQ];
__device__ int   g_off[NQ + 1];
__device__ int   g_cur[NQ];
__device__ int   g_idx[NK];

// ---------------- PTX helpers (portable sm_80+) ----------------
__device__ __forceinline__ void cp16(uint32_t dst, const void* src) {
    asm volatile("cp.async.cg.shared.global [%0], [%1], 16;" :: "r"(dst), "l"(src));
}
__device__ __forceinline__ void cp_commit() {
    asm volatile("cp.async.commit_group;" ::: "memory");
}
template <int N> __device__ __forceinline__ void cp_wait() {
    asm volatile("cp.async.wait_group %0;" :: "n"(N) : "memory");
}
__device__ __forceinline__ void ldsm4(uint32_t* r, uint32_t addr) {
    asm volatile("ldmatrix.sync.aligned.m8n8.x4.shared.b16 {%0,%1,%2,%3}, [%4];"
                 : "=r"(r[0]), "=r"(r[1]), "=r"(r[2]), "=r"(r[3]) : "r"(addr));
}
__device__ __forceinline__ void mma16816(float* c, const uint32_t* a, const uint32_t* b) {
    asm volatile(
        "mma.sync.aligned.m16n8k16.row.col.f32.f16.f16.f32 "
        "{%0,%1,%2,%3}, {%4,%5,%6,%7}, {%8,%9}, {%0,%1,%2,%3};"
        : "+f"(c[0]), "+f"(c[1]), "+f"(c[2]), "+f"(c[3])
        : "r"(a[0]), "r"(a[1]), "r"(a[2]), "r"(a[3]), "r"(b[0]), "r"(b[1]));
}

#define TILE_B   8192
#define STAGE_B  (3 * TILE_B)          // narrow 2-term stage: Ah, Al, B
#define NSTAGE   4
#define GEMM_SMEM (NSTAGE * STAGE_B)   // 98304

// wide single-term stage: A (8KB) + B256 (16KB) = 24576 = STAGE_B (same total)

// ---------------- narrow GEMM body (2-term, CTA 128x128, warp 64x32) ----------
__device__ __forceinline__ void gemm_body2(
    int bx, int by,
    const __half* __restrict__ Ah, const __half* __restrict__ Al,
    const __half* __restrict__ B, const float* __restrict__ bias,
    __half* __restrict__ Ch, int ldc, int kdim)
{
    extern __shared__ char smem[];
    const uint32_t sb = (uint32_t)__cvta_generic_to_shared(smem);
    const int tid = threadIdx.x, wid = tid >> 5, lane = tid & 31;
    const int warp_m = wid & 1, warp_n = wid >> 1;
    const int m_base = by * 128;
    const int n_base = bx * 128;

    float acc[4][4][4];
    #pragma unroll
    for (int i = 0; i < 4; i++)
        #pragma unroll
        for (int j = 0; j < 4; j++)
            #pragma unroll
            for (int k = 0; k < 4; k++) acc[i][j][k] = 0.0f;

    const int fr0 = tid >> 2, fc0 = tid & 3;
    const int fr1 = fr0 + 64;
    const uint32_t fd0 = (uint32_t)(fr0 * 64 + ((fc0 ^ ((fr0 >> 1) & 3)) << 4));
    const uint32_t fd1 = (uint32_t)(fr1 * 64 + ((fc0 ^ ((fr1 >> 1) & 3)) << 4));

    auto issue_loads = [&](int gi) {
        const int koff = gi * 32, s = gi & 3;
        const uint32_t st = sb + s * STAGE_B;
        const size_t aoff = (size_t)m_base * kdim + koff + fc0 * 8;
        const size_t boff = (size_t)n_base * kdim + koff + fc0 * 8;
        cp16(st + fd0,              Ah + aoff + (size_t)fr0 * kdim);
        cp16(st + fd1,              Ah + aoff + (size_t)fr1 * kdim);
        cp16(st + TILE_B + fd0,     Al + aoff + (size_t)fr0 * kdim);
        cp16(st + TILE_B + fd1,     Al + aoff + (size_t)fr1 * kdim);
        cp16(st + 2 * TILE_B + fd0, B + boff + (size_t)fr0 * kdim);
        cp16(st + 2 * TILE_B + fd1, B + boff + (size_t)fr1 * kdim);
        cp_commit();
    };

    issue_loads(0);
    issue_loads(1);
    issue_loads(2);

    const int a_row = warp_m * 64 + (lane & 15);
    const int a_half = lane >> 4;
    const int a_s = ((lane & 15) >> 1) & 3;
    const int b_row = warp_n * 32 + ((lane >> 4) << 3) + (lane & 7);
    const int b_half = (lane >> 3) & 1;
    const int b_s = ((lane & 7) >> 1) & 3;

    const int NSTEP = kdim / 32;
    for (int gi = 0; gi < NSTEP; gi++) {
        if (gi + 3 < NSTEP) cp_wait<2>(); else cp_wait<0>();
        __syncthreads();
        if (gi + 3 < NSTEP) issue_loads(gi + 3);

        const uint32_t st = sb + (gi & 3) * STAGE_B;
        const uint32_t sAh = st, sAl = st + TILE_B, sB = st + 2 * TILE_B;

        #pragma unroll
        for (int kh = 0; kh < 2; kh++) {
            const uint32_t acb = (uint32_t)(((kh * 2 + a_half) ^ a_s) << 4);
            const uint32_t bcb = (uint32_t)(((kh * 2 + b_half) ^ b_s) << 4);
            uint32_t bf[2][4], af[4][4];
            #pragma unroll
            for (int nf2 = 0; nf2 < 2; nf2++)
                ldsm4(bf[nf2], sB + (uint32_t)((b_row + nf2 * 16) * 64) + bcb);
            #pragma unroll
            for (int mf = 0; mf < 4; mf++)
                ldsm4(af[mf], sAh + (uint32_t)((a_row + mf * 16) * 64) + acb);
            #pragma unroll
            for (int mf = 0; mf < 4; mf++)
                #pragma unroll
                for (int nf = 0; nf < 4; nf++)
                    mma16816(acc[mf][nf], af[mf], &bf[nf >> 1][(nf & 1) * 2]);
            #pragma unroll
            for (int mf = 0; mf < 4; mf++)
                ldsm4(af[mf], sAl + (uint32_t)((a_row + mf * 16) * 64) + acb);
            #pragma unroll
            for (int mf = 0; mf < 4; mf++)
                #pragma unroll
                for (int nf = 0; nf < 4; nf++)
                    mma16816(acc[mf][nf], af[mf], &bf[nf >> 1][(nf & 1) * 2]);
        }
    }

    const int col0 = n_base + warp_n * 32 + (lane & 3) * 2;
    const int r0   = m_base + warp_m * 64 + (lane >> 2);
    #pragma unroll
    for (int mf = 0; mf < 4; mf++) {
        const int ra = r0 + mf * 16, rb = ra + 8;
        #pragma unroll
        for (int nf = 0; nf < 4; nf++) {
            const int col = col0 + nf * 8;
            const float b0 = bias[col], b1 = bias[col + 1];
            __half2 ha = {__float2half(acc[mf][nf][0] + b0), __float2half(acc[mf][nf][1] + b1)};
            __half2 hb = {__float2half(acc[mf][nf][2] + b0), __float2half(acc[mf][nf][3] + b1)};
            *(__half2*)(Ch + (size_t)ra * ldc + col) = ha;
            *(__half2*)(Ch + (size_t)rb * ldc + col) = hb;
        }
    }
}

// ---------------- wide GEMM body (single-term, CTA 128x256, warp 64x64) --------
template <bool HALF_OUT>
__device__ __forceinline__ void gemm_wide(
    int bx, int by,
    const __half* __restrict__ A, const __half* __restrict__ B,
    const float* __restrict__ bias, float* __restrict__ Cf,
    __half* __restrict__ Ch, const int* __restrict__ cnt, int ldc, int kdim)
{
    extern __shared__ char smem[];
    const uint32_t sb = (uint32_t)__cvta_generic_to_shared(smem);
    const int tid = threadIdx.x, wid = tid >> 5, lane = tid & 31;
    const int warp_m = wid & 1, warp_n = wid >> 1;
    const int m_base = by * 128;
    const int n_base = bx * 256;

    float acc[4][8][4];
    #pragma unroll
    for (int i = 0; i < 4; i++)
        #pragma unroll
        for (int j = 0; j < 8; j++)
            #pragma unroll
            for (int k = 0; k < 4; k++) acc[i][j][k] = 0.0f;

    const int fr = tid >> 2, fc = tid & 3;
    const uint32_t fdA0 = (uint32_t)(fr * 64        + ((fc ^ ((fr >> 1) & 3)) << 4));
    const uint32_t fdA1 = (uint32_t)((fr + 64) * 64 + ((fc ^ (((fr + 64) >> 1) & 3)) << 4));

    auto issue_loads = [&](int gi) {
        const int koff = gi * 32, s = gi & 3;
        const uint32_t st = sb + s * STAGE_B;          // A 8KB | B 16KB
        const size_t aoff = (size_t)m_base * kdim + koff + fc * 8;
        const size_t boff = (size_t)n_base * kdim + koff + fc * 8;
        cp16(st + fdA0, A + aoff + (size_t)fr * kdim);
        cp16(st + fdA1, A + aoff + (size_t)(fr + 64) * kdim);
        const uint32_t sB = st + TILE_B;
        #pragma unroll
        for (int rb = 0; rb < 4; rb++) {
            const int r = fr + rb * 64;
            cp16(sB + (uint32_t)(r * 64 + ((fc ^ ((r >> 1) & 3)) << 4)),
                 B + boff + (size_t)r * kdim);
        }
        cp_commit();
    };

    issue_loads(0);
    issue_loads(1);
    issue_loads(2);

    const int a_row = warp_m * 64 + (lane & 15);
    const int a_half = lane >> 4;
    const int a_s = ((lane & 15) >> 1) & 3;
    const int b_row = warp_n * 64 + ((lane >> 4) << 3) + (lane & 7);
    const int b_half = (lane >> 3) & 1;
    const int b_s = ((lane & 7) >> 1) & 3;

    const int NSTEP = kdim / 32;
    for (int gi = 0; gi < NSTEP; gi++) {
        if (gi + 3 < NSTEP) cp_wait<2>(); else cp_wait<0>();
        __syncthreads();
        if (gi + 3 < NSTEP) issue_loads(gi + 3);

        const uint32_t st = sb + (gi & 3) * STAGE_B;
        const uint32_t sA = st, sB = st + TILE_B;

        #pragma unroll
        for (int kh = 0; kh < 2; kh++) {
            const uint32_t acb = (uint32_t)(((kh * 2 + a_half) ^ a_s) << 4);
            const uint32_t bcb = (uint32_t)(((kh * 2 + b_half) ^ b_s) << 4);
            uint32_t bf[4][4], af[4][4];
            #pragma unroll
            for (int nf2 = 0; nf2 < 4; nf2++)
                ldsm4(bf[nf2], sB + (uint32_t)((b_row + nf2 * 16) * 64) + bcb);
            #pragma unroll
            for (int mf = 0; mf < 4; mf++)
                ldsm4(af[mf], sA + (uint32_t)((a_row + mf * 16) * 64) + acb);
            #pragma unroll
            for (int mf = 0; mf < 4; mf++)
                #pragma unroll
                for (int nf = 0; nf < 8; nf++)
                    mma16816(acc[mf][nf], af[mf], &bf[nf >> 1][(nf & 1) * 2]);
        }
    }

    const int col0 = n_base + warp_n * 64 + (lane & 3) * 2;
    const int r0   = m_base + warp_m * 64 + (lane >> 2);
    #pragma unroll
    for (int mf = 0; mf < 4; mf++) {
        const int ra = r0 + mf * 16, rb = ra + 8;
        const bool za = cnt && (cnt[ra] == 0);
        const bool zbm = cnt && (cnt[rb] == 0);
        #pragma unroll
        for (int nf = 0; nf < 8; nf++) {
            const int col = col0 + nf * 8;
            const float b0 = bias[col], b1 = bias[col + 1];
            float v0 = za ? 0.f : acc[mf][nf][0] + b0;
            float v1 = za ? 0.f : acc[mf][nf][1] + b1;
            float v2 = zbm ? 0.f : acc[mf][nf][2] + b0;
            float v3 = zbm ? 0.f : acc[mf][nf][3] + b1;
            if (HALF_OUT) {
                __half2 ha = {__float2half(v0), __float2half(v1)};
                __half2 hb = {__float2half(v2), __float2half(v3)};
                *(__half2*)(Ch + (size_t)ra * ldc + col) = ha;
                *(__half2*)(Ch + (size_t)rb * ldc + col) = hb;
            } else {
                *(float2*)(Cf + (size_t)ra * ldc + col) = make_float2(v0, v1);
                *(float2*)(Cf + (size_t)rb * ldc + col) = make_float2(v2, v3);
            }
        }
    }
}

// ---------------- fuseA: split-Wk | conv-Wq | wtrans-Wv | zero_cnt | vecprep ----
__global__ void fuseA_kernel(const float* __restrict__ Wq, const float* __restrict__ Wk,
                             const float* __restrict__ Wv, const float* __restrict__ bq,
                             const float* __restrict__ bk)
{
    const int b = blockIdx.x, tid = threadIdx.x;
    if (b < 512) {                       // Wk fp32 -> hi/lo split
        const size_t i = 4 * ((size_t)b * 256 + tid);
        float4 v = *(const float4*)(Wk + i);
        __half h0 = __float2half(v.x), h1 = __float2half(v.y);
        __half h2 = __float2half(v.z), h3 = __float2half(v.w);
        __half2 hp0 = {h0, h1}, hp1 = {h2, h3};
        __half2 lp0 = {__float2half(v.x - __half2float(h0)), __float2half(v.y - __half2float(h1))};
        __half2 lp1 = {__float2half(v.z - __half2float(h2)), __float2half(v.w - __half2float(h3))};
        *(__half2*)(g_Wkh + i)     = hp0;
        *(__half2*)(g_Wkh + i + 2) = hp1;
        *(__half2*)(g_Wkl + i)     = lp0;
        *(__half2*)(g_Wkl + i + 2) = lp1;
    } else if (b < 1024) {               // Wq fp32 -> fp16
        const size_t i = 4 * ((size_t)(b - 512) * 256 + tid);
        float4 v = *(const float4*)(Wq + i);
        __half2 p0 = {__float2half(v.x), __float2half(v.y)};
        __half2 p1 = {__float2half(v.z), __float2half(v.w)};
        *(__half2*)(g_Wqf + i)     = p0;
        *(__half2*)(g_Wqf + i + 2) = p1;
    } else if (b < 1536) {               // Wv[k][n] -> WvT[n][k] fp16
        __shared__ float tile[32][33];
        const int bb = b - 1024;
        const int n0 = (bb & 15) * 32, k0 = (bb >> 4) * 32;
        const int tx = tid & 31, ty0 = tid >> 5;
        #pragma unroll
        for (int i = 0; i < 4; i++) {
            const int ty = ty0 + 8 * i;
            tile[ty][tx] = Wv[(size_t)(k0 + ty) * 512 + (n0 + tx)];
        }
        __syncthreads();
        #pragma unroll
        for (int i = 0; i < 4; i++) {
            const int ty = ty0 + 8 * i;
            g_WvT[(size_t)(n0 + ty) * DIN + (k0 + tx)] = __float2half(tile[tx][ty]);
        }
    } else if (b < 1552) {               // zero g_cnt
        g_cnt[(b - 1536) * 256 + tid] = 0;
    } else {                             // vecprep: bqWk, wqbk, bqbk
        const int gw = (b - 1552) * 8 + (tid >> 5);
        const int lane = tid & 31;
        const float* rowp; const float* vecp; float* outp;
        if (gw < DIN)            { rowp = Wk + (size_t)gw * 512;         vecp = bq; outp = g_bqWk + gw; }
        else if (gw < 2 * DIN)   { rowp = Wq + (size_t)(gw - DIN) * 512; vecp = bk; outp = g_wqbk + (gw - DIN); }
        else if (gw == 2 * DIN)  { rowp = bq;                            vecp = bk; outp = g_bqbk; }
        else return;
        const float4* r4 = (const float4*)rowp;
        const float4* v4 = (const float4*)vecp;
        float d = 0.f;
        #pragma unroll
        for (int it = 0; it < 4; it++) {
            float4 a = r4[lane + 32 * it], bb2 = v4[lane + 32 * it];
            d += a.x * bb2.x + a.y * bb2.y + a.z * bb2.z + a.w * bb2.w;
        }
        #pragma unroll
        for (int off = 16; off > 0; off >>= 1) d += __shfl_down_sync(0xFFFFFFFFu, d, off);
        if (lane == 0) *outp = d;
    }
}

// ---------------- fuseBC: G-GEMM | hist | X1 split (hi only) + c0 --------------
__global__ __launch_bounds__(256, 2)
void fuseBC_kernel(const int* __restrict__ row_map, const float* __restrict__ X1)
{
    const int b = blockIdx.x, t = threadIdx.x;
    if (b < 64) {                        // Gt = Wk . Wq^T (M=1024,N=1024,K=512) -> fp16
        gemm_body2(b & 7, b >> 3, g_Wkh, g_Wkl, g_Wqf, g_zb, g_Gh, DIN, 512);
        return;
    }
    if (b < 192) {                       // histogram
        atomicAdd(&g_cnt[row_map[(b - 64) * 256 + t]], 1);
        return;
    }
    __shared__ float sred[8];
    const int row = b - 192;
    const size_t i = (size_t)row * DIN + t * 4;
    float4 v = *(const float4*)(X1 + i);
    __half2 hp0 = {__float2half(v.x), __float2half(v.y)};
    __half2 hp1 = {__float2half(v.z), __float2half(v.w)};
    *(__half2*)(g_X1h + i)     = hp0;
    *(__half2*)(g_X1h + i + 2) = hp1;
    const float4 w = *(const float4*)(g_wqbk + t * 4);
    float d = v.x * w.x + v.y * w.y + v.z * w.z + v.w * w.w;
    #pragma unroll
    for (int off = 16; off > 0; off >>= 1) d += __shfl_down_sync(0xFFFFFFFFu, d, off);
    if ((t & 31) == 0) sred[t >> 5] = d;
    __syncthreads();
    if (t < 8) {
        float s = sred[t];
        #pragma unroll
        for (int off = 4; off > 0; off >>= 1) s += __shfl_down_sync(0xFFu, s, off);
        if (t == 0) g_c0[row] = s + g_bqbk[0];
    }
}

// ---------------- scan: 1 block, 256 threads, 16 elems/thread ----------------
__global__ void scan_kernel() {
    __shared__ int wsum[8];
    const int t = threadIdx.x;
    int v[16];
    #pragma unroll
    for (int q = 0; q < 4; q++) {
        int4 c = *(const int4*)&g_cnt[16 * t + 4 * q];
        v[4 * q] = c.x; v[4 * q + 1] = c.y; v[4 * q + 2] = c.z; v[4 * q + 3] = c.w;
    }
    int run = 0;
    #pragma unroll
    for (int i = 0; i < 16; i++) { const int tmp = v[i]; v[i] = run; run += tmp; }
    const int lane = t & 31, w = t >> 5;
    int incl = run;
    #pragma unroll
    for (int off = 1; off < 32; off <<= 1) {
        const int n = __shfl_up_sync(0xFFFFFFFFu, incl, off);
        if (lane >= off) incl += n;
    }
    if (lane == 31) wsum[w] = incl;
    const int lane_excl = incl - run;
    __syncthreads();
    if (t < 8) {
        const int o = wsum[t];
        int s = o;
        #pragma unroll
        for (int off = 1; off < 8; off <<= 1) {
            const int n = __shfl_up_sync(0xFFu, s, off);
            if (t >= off) s += n;
        }
        wsum[t] = s - o;
    }
    __syncthreads();
    const int base = wsum[w] + lane_excl;
    #pragma unroll
    for (int i = 0; i < 16; i++) {
        const int o = base + v[i];
        g_off[16 * t + i] = o;
        g_cur[16 * t + i] = o;
    }
    if (t == 255) g_off[NQ] = base + run;
}

// ---------------- fuseD: U-GEMM (wide single-term, fp16 out) | fill ------------
// grid = 128 + 128 blocks x 256, dyn smem GEMM_SMEM
__global__ __launch_bounds__(256, 1)
void fuseD_kernel(const int* __restrict__ row_map)
{
    const int b = blockIdx.x;
    if (b < 128) {                       // U = X1h . G + bq.Wk^T (M=4096,N=1024,K=1024)
        gemm_wide<true>(b & 3, b >> 2, g_X1h, g_Gh, g_bqWk,
                        nullptr, g_Uh, nullptr, DIN, 1024);
        return;
    }
    const int j = (b - 128) * 256 + threadIdx.x;
    const int pos = atomicAdd(&g_cur[row_map[j]], 1);
    g_idx[pos] = j;
}

// ---------------- C-GEMM: wide single-term, fp32 out, cnt mask ----------------
__global__ __launch_bounds__(256, 1)
void cgemm_kernel(const float* __restrict__ bv, float* __restrict__ out)
{
    gemm_wide<false>(blockIdx.x, blockIdx.y, g_Yh, g_WvT, bv,
                     out, nullptr, g_cnt, 512, 1024);
}

// ---------------- fused attention: scores + online softmax + Y (fp16) ----------
#define CH 64
__global__ void attn_kernel(const float* __restrict__ X2) {
    __shared__ float ssc[CH];
    const int qi = blockIdx.x;
    const int s = g_off[qi], e = g_off[qi + 1];
    const int t = threadIdx.x, wid = t >> 5, lane = t & 31;
    const size_t yo = (size_t)qi * DIN + t * 4;
    if (e == s) {
        __half2 z = {__float2half(0.f), __float2half(0.f)};
        *(__half2*)(g_Yh + yo) = z; *(__half2*)(g_Yh + yo + 2) = z;
        return;
    }
    const float c0 = g_c0[qi];
    const uint2* uu = (const uint2*)(g_Uh + (size_t)qi * DIN);
    float m = -1e30f, den = 0.f;
    float4 acc = make_float4(0.f, 0.f, 0.f, 0.f);

    for (int t0 = s; t0 < e; t0 += CH) {
        const int nt = min(CH, e - t0);
        for (int tt = wid; tt < nt; tt += 8) {
            const int j = g_idx[t0 + tt];
            const float4* x4 = (const float4*)(X2 + (size_t)j * DIN);
            float d = 0.f;
            #pragma unroll
            for (int it = 0; it < 8; it++) {
                float4 a = x4[lane + 32 * it];
                uint2 p = uu[lane + 32 * it];
                float2 f01 = __half22float2(*(__half2*)&p.x);
                float2 f23 = __half22float2(*(__half2*)&p.y);
                d += a.x * f01.x + a.y * f01.y + a.z * f23.x + a.w * f23.y;
            }
            #pragma unroll
            for (int off = 16; off > 0; off >>= 1)
                d += __shfl_down_sync(0xFFFFFFFFu, d, off);
            if (lane == 0) ssc[tt] = (d + c0) * 0.044194173824159216f;
        }
        __syncthreads();
        float mc = -1e30f;
        for (int k = 0; k < nt; k++) mc = fmaxf(mc, ssc[k]);
        const float mnew = fmaxf(m, mc);
        const float resc = expf(m - mnew);
        den *= resc;
        acc.x *= resc; acc.y *= resc; acc.z *= resc; acc.w *= resc;
        for (int k = 0; k < nt; k++) {
            const int j = g_idx[t0 + k];
            const float w = expf(ssc[k] - mnew);
            den += w;
            const float4 v = *(const float4*)(X2 + (size_t)j * DIN + t * 4);
            acc.x += w * v.x; acc.y += w * v.y; acc.z += w * v.z; acc.w += w * v.w;
        }
        m = mnew;
        __syncthreads();
    }
    const float inv = 1.0f / den;
    __half2 hp0 = {__float2half(acc.x * inv), __float2half(acc.y * inv)};
    __half2 hp1 = {__float2half(acc.z * inv), __float2half(acc.w * inv)};
    *(__half2*)(g_Yh + yo)     = hp0;
    *(__half2*)(g_Yh + yo + 2) = hp1;
}

// ---------------- launcher ----------------
extern "C" void kernel_launch(void* const* d_in, const int* in_sizes, int n_in,
                              void* d_out, int out_size)
{
    const float* X1 = (const float*)d_in[0];
    const float* X2 = (const float*)d_in[1];
    const float* Wq = (const float*)d_in[2];
    const float* bq = (const float*)d_in[3];
    const float* Wk = (const float*)d_in[4];
    const float* bk = (const float*)d_in[5];
    const float* Wv = (const float*)d_in[6];
    const float* bv = (const float*)d_in[7];
    const int*   row_map = (const int*)d_in[8];
    float* out = (float*)d_out;

    cudaFuncSetAttribute(fuseBC_kernel, cudaFuncAttributeMaxDynamicSharedMemorySize, GEMM_SMEM);
    cudaFuncSetAttribute(fuseD_kernel,  cudaFuncAttributeMaxDynamicSharedMemorySize, GEMM_SMEM);
    cudaFuncSetAttribute(cgemm_kernel,  cudaFuncAttributeMaxDynamicSharedMemorySize, GEMM_SMEM);

    // 1. independent prep + zero_cnt
    fuseA_kernel<<<1809, 256>>>(Wq, Wk, Wv, bq, bk);
    // 2. G-GEMM | hist | X1-split + c0
    fuseBC_kernel<<<4288, 256, GEMM_SMEM>>>(row_map, X1);
    // 3. scan (tiny)
    scan_kernel<<<1, 256>>>();
    // 4. U-GEMM (wide, fp16 out) | fill
    fuseD_kernel<<<256, 256, GEMM_SMEM>>>(row_map);
    // 5. fused attention -> Yh (fp16)
    attn_kernel<<<NQ, 256>>>(X2);
    // 6. C = Yh . Wv + bv (wide single-term), empty rows zeroed
    cgemm_kernel<<<dim3(2, 32), 256, GEMM_SMEM>>>(bv, out);
}

// round 14
// speedup vs baseline: 1.0934x; 1.0934x over previous
#include <cuda_runtime.h>
#include <cuda_fp16.h>
#include <math.h>
#include <stdint.h>

#define NQ 4096
#define NK 32768
#define DIN 1024
#define DQK 512
#define DV 512

// ---------------- scratch (no allocations allowed) ----------------
__device__ __half g_X1h[(size_t)NQ * DIN];
__device__ __half g_Yh[(size_t)NQ * DIN];
__device__ __half g_Uh[(size_t)NQ * DIN];     // U = X1.G + bq.Wk^T (fp16)
__device__ __half g_Wkh[(size_t)DIN * 512];   // Wk split hi   [d2][c]
__device__ __half g_Wkl[(size_t)DIN * 512];   // Wk split lo
__device__ __half g_Wqf[(size_t)DIN * 512];   // fl16(Wq)      [d1][c]
__device__ __half g_WvT[(size_t)512 * DIN];   // Wv^T [n][k] fp16
__device__ __half g_Gh[(size_t)DIN * DIN];    // Gt = Wk.Wq^T, fp16
__device__ float g_c0[NQ];                    // Q[i].bk
__device__ float g_bqWk[DIN];
__device__ float g_wqbk[DIN];
__device__ float g_bqbk[1];
__device__ float g_zb[DIN];                   // zero bias (never written)
__device__ int   g_cnt[NQ];
__device__ int   g_off[NQ + 1];
__device__ int   g_cur[NQ];
__device__ int   g_idx[NK];

// ---------------- PTX helpers (portable sm_80+) ----------------
__device__ __forceinline__ void cp16(uint32_t dst, const void* src) {
    asm volatile("cp.async.cg.shared.global [%0], [%1], 16;" :: "r"(dst), "l"(src));
}
__device__ __forceinline__ void cp_commit() {
    asm volatile("cp.async.commit_group;" ::: "memory");
}
template <int N> __device__ __forceinline__ void cp_wait() {
    asm volatile("cp.async.wait_group %0;" :: "n"(N) : "memory");
}
__device__ __forceinline__ void ldsm4(uint32_t* r, uint32_t addr) {
    asm volatile("ldmatrix.sync.aligned.m8n8.x4.shared.b16 {%0,%1,%2,%3}, [%4];"
                 : "=r"(r[0]), "=r"(r[1]), "=r"(r[2]), "=r"(r[3]) : "r"(addr));
}
__device__ __forceinline__ void mma16816(float* c, const uint32_t* a, const uint32_t* b) {
    asm volatile(
        "mma.sync.aligned.m16n8k16.row.col.f32.f16.f16.f32 "
        "{%0,%1,%2,%3}, {%4,%5,%6,%7}, {%8,%9}, {%0,%1,%2,%3};"
        : "+f"(c[0]), "+f"(c[1]), "+f"(c[2]), "+f"(c[3])
        : "r"(a[0]), "r"(a[1]), "r"(a[2]), "r"(a[3]), "r"(b[0]), "r"(b[1]));
}

#define TILE_B   8192
#define STAGE_B  (3 * TILE_B)
#define NSTAGE   4
#define GEMM_SMEM (NSTAGE * STAGE_B)   // 98304

// ---------------- GEMM body (R12-proven): C = (Ah [+ Al]) * B^T + bias --------
template <bool TWO>
__device__ __forceinline__ void gemm_body(
    int bx, int by,
    const __half* __restrict__ Ah, const __half* __restrict__ Al,
    const __half* __restrict__ B, const float* __restrict__ bias,
    float* __restrict__ Cf, __half* __restrict__ Ch,
    const int* __restrict__ cnt, int ldc, int kdim)
{
    extern __shared__ char smem[];
    const uint32_t sb = (uint32_t)__cvta_generic_to_shared(smem);
    const int tid = threadIdx.x, wid = tid >> 5, lane = tid & 31;
    const int warp_m = wid & 1, warp_n = wid >> 1;
    const int m_base = by * 128;
    const int n_base = bx * 128;

    float acc[4][4][4];
    #pragma unroll
    for (int i = 0; i < 4; i++)
        #pragma unroll
        for (int j = 0; j < 4; j++)
            #pragma unroll
            for (int k = 0; k < 4; k++) acc[i][j][k] = 0.0f;

    const int fr0 = tid >> 2, fc0 = tid & 3;
    const int fr1 = fr0 + 64;
    const uint32_t fd0 = (uint32_t)(fr0 * 64 + ((fc0 ^ ((fr0 >> 1) & 3)) << 4));
    const uint32_t fd1 = (uint32_t)(fr1 * 64 + ((fc0 ^ ((fr1 >> 1) & 3)) << 4));

    auto issue_loads = [&](int gi) {
        const int koff = gi * 32, s = gi & 3;
        const uint32_t st = sb + s * STAGE_B;
        const size_t aoff = (size_t)m_base * kdim + koff + fc0 * 8;
        const size_t boff = (size_t)n_base * kdim + koff + fc0 * 8;
        cp16(st + fd0,              Ah + aoff + (size_t)fr0 * kdim);
        cp16(st + fd1,              Ah + aoff + (size_t)fr1 * kdim);
        if (TWO) {
            cp16(st + TILE_B + fd0, Al + aoff + (size_t)fr0 * kdim);
            cp16(st + TILE_B + fd1, Al + aoff + (size_t)fr1 * kdim);
        }
        cp16(st + 2 * TILE_B + fd0, B + boff + (size_t)fr0 * kdim);
        cp16(st + 2 * TILE_B + fd1, B + boff + (size_t)fr1 * kdim);
        cp_commit();
    };

    issue_loads(0);
    issue_loads(1);
    issue_loads(2);

    const int a_row = warp_m * 64 + (lane & 15);
    const int a_half = lane >> 4;
    const int a_s = ((lane & 15) >> 1) & 3;
    const int b_row = warp_n * 32 + ((lane >> 4) << 3) + (lane & 7);
    const int b_half = (lane >> 3) & 1;
    const int b_s = ((lane & 7) >> 1) & 3;

    const int NSTEP = kdim / 32;
    for (int gi = 0; gi < NSTEP; gi++) {
        if (gi + 3 < NSTEP) cp_wait<2>(); else cp_wait<0>();
        __syncthreads();
        if (gi + 3 < NSTEP) issue_loads(gi + 3);

        const uint32_t st = sb + (gi & 3) * STAGE_B;
        const uint32_t sAh = st, sAl = st + TILE_B, sB = st + 2 * TILE_B;

        #pragma unroll
        for (int kh = 0; kh < 2; kh++) {
            const uint32_t acb = (uint32_t)(((kh * 2 + a_half) ^ a_s) << 4);
            const uint32_t bcb = (uint32_t)(((kh * 2 + b_half) ^ b_s) << 4);
            uint32_t bf[2][4], af[4][4];
            #pragma unroll
            for (int nf2 = 0; nf2 < 2; nf2++)
                ldsm4(bf[nf2], sB + (uint32_t)((b_row + nf2 * 16) * 64) + bcb);
            #pragma unroll
            for (int mf = 0; mf < 4; mf++)
                ldsm4(af[mf], sAh + (uint32_t)((a_row + mf * 16) * 64) + acb);
            #pragma unroll
            for (int mf = 0; mf < 4; mf++)
                #pragma unroll
                for (int nf = 0; nf < 4; nf++)
                    mma16816(acc[mf][nf], af[mf], &bf[nf >> 1][(nf & 1) * 2]);
            if (TWO) {
                #pragma unroll
                for (int mf = 0; mf < 4; mf++)
                    ldsm4(af[mf], sAl + (uint32_t)((a_row + mf * 16) * 64) + acb);
                #pragma unroll
                for (int mf = 0; mf < 4; mf++)
                    #pragma unroll
                    for (int nf = 0; nf < 4; nf++)
                        mma16816(acc[mf][nf], af[mf], &bf[nf >> 1][(nf & 1) * 2]);
            }
        }
    }

    const int col0 = n_base + warp_n * 32 + (lane & 3) * 2;
    const int r0   = m_base + warp_m * 64 + (lane >> 2);
    #pragma unroll
    for (int mf = 0; mf < 4; mf++) {
        const int ra = r0 + mf * 16, rb = ra + 8;
        const bool za = cnt && (cnt[ra] == 0);
        const bool zbm = cnt && (cnt[rb] == 0);
        #pragma unroll
        for (int nf = 0; nf < 4; nf++) {
            const int col = col0 + nf * 8;
            const float b0 = bias[col], b1 = bias[col + 1];
            float v0 = za ? 0.f : acc[mf][nf][0] + b0;
            float v1 = za ? 0.f : acc[mf][nf][1] + b1;
            float v2 = zbm ? 0.f : acc[mf][nf][2] + b0;
            float v3 = zbm ? 0.f : acc[mf][nf][3] + b1;
            if (Ch) {
                __half2 ha = {__float2half(v0), __float2half(v1)};
                __half2 hb = {__float2half(v2), __float2half(v3)};
                *(__half2*)(Ch + (size_t)ra * ldc + col) = ha;
                *(__half2*)(Ch + (size_t)rb * ldc + col) = hb;
            } else {
                *(float2*)(Cf + (size_t)ra * ldc + col) = make_float2(v0, v1);
                *(float2*)(Cf + (size_t)rb * ldc + col) = make_float2(v2, v3);
            }
        }
    }
}

// ---------------- fuseA: split-Wk | conv-Wq | wtrans-Wv | zero_cnt | vecprep ----
__global__ void fuseA_kernel(const float* __restrict__ Wq, const float* __restrict__ Wk,
                             const float* __restrict__ Wv, const float* __restrict__ bq,
                             const float* __restrict__ bk)
{
    const int b = blockIdx.x, tid = threadIdx.x;
    if (b < 512) {                       // Wk fp32 -> hi/lo split
        const size_t i = 4 * ((size_t)b * 256 + tid);
        float4 v = *(const float4*)(Wk + i);
        __half h0 = __float2half(v.x), h1 = __float2half(v.y);
        __half h2 = __float2half(v.z), h3 = __float2half(v.w);
        __half2 hp0 = {h0, h1}, hp1 = {h2, h3};
        __half2 lp0 = {__float2half(v.x - __half2float(h0)), __float2half(v.y - __half2float(h1))};
        __half2 lp1 = {__float2half(v.z - __half2float(h2)), __float2half(v.w - __half2float(h3))};
        *(__half2*)(g_Wkh + i)     = hp0;
        *(__half2*)(g_Wkh + i + 2) = hp1;
        *(__half2*)(g_Wkl + i)     = lp0;
        *(__half2*)(g_Wkl + i + 2) = lp1;
    } else if (b < 1024) {               // Wq fp32 -> fp16
        const size_t i = 4 * ((size_t)(b - 512) * 256 + tid);
        float4 v = *(const float4*)(Wq + i);
        __half2 p0 = {__float2half(v.x), __float2half(v.y)};
        __half2 p1 = {__float2half(v.z), __float2half(v.w)};
        *(__half2*)(g_Wqf + i)     = p0;
        *(__half2*)(g_Wqf + i + 2) = p1;
    } else if (b < 1536) {               // Wv[k][n] -> WvT[n][k] fp16
        __shared__ float tile[32][33];
        const int bb = b - 1024;
        const int n0 = (bb & 15) * 32, k0 = (bb >> 4) * 32;
        const int tx = tid & 31, ty0 = tid >> 5;
        #pragma unroll
        for (int i = 0; i < 4; i++) {
            const int ty = ty0 + 8 * i;
            tile[ty][tx] = Wv[(size_t)(k0 + ty) * 512 + (n0 + tx)];
        }
        __syncthreads();
        #pragma unroll
        for (int i = 0; i < 4; i++) {
            const int ty = ty0 + 8 * i;
            g_WvT[(size_t)(n0 + ty) * DIN + (k0 + tx)] = __float2half(tile[tx][ty]);
        }
    } else if (b < 1552) {               // zero g_cnt
        g_cnt[(b - 1536) * 256 + tid] = 0;
    } else {                             // vecprep: bqWk, wqbk, bqbk
        const int gw = (b - 1552) * 8 + (tid >> 5);
        const int lane = tid & 31;
        const float* rowp; const float* vecp; float* outp;
        if (gw < DIN)            { rowp = Wk + (size_t)gw * 512;         vecp = bq; outp = g_bqWk + gw; }
        else if (gw < 2 * DIN)   { rowp = Wq + (size_t)(gw - DIN) * 512; vecp = bk; outp = g_wqbk + (gw - DIN); }
        else if (gw == 2 * DIN)  { rowp = bq;                            vecp = bk; outp = g_bqbk; }
        else return;
        const float4* r4 = (const float4*)rowp;
        const float4* v4 = (const float4*)vecp;
        float d = 0.f;
        #pragma unroll
        for (int it = 0; it < 4; it++) {
            float4 a = r4[lane + 32 * it], bb2 = v4[lane + 32 * it];
            d += a.x * bb2.x + a.y * bb2.y + a.z * bb2.z + a.w * bb2.w;
        }
        #pragma unroll
        for (int off = 16; off > 0; off >>= 1) d += __shfl_down_sync(0xFFFFFFFFu, d, off);
        if (lane == 0) *outp = d;
    }
}

// ---------------- fuseBC: G-GEMM | hist | X1 split (hi only) + c0 --------------
__global__ __launch_bounds__(256, 2)
void fuseBC_kernel(const int* __restrict__ row_map, const float* __restrict__ X1)
{
    const int b = blockIdx.x, t = threadIdx.x;
    if (b < 64) {                        // Gt = Wk . Wq^T (M=1024,N=1024,K=512) -> fp16
        gemm_body<true>(b & 7, b >> 3, g_Wkh, g_Wkl, g_Wqf, g_zb,
                        nullptr, g_Gh, nullptr, DIN, 512);
        return;
    }
    if (b < 192) {                       // histogram
        atomicAdd(&g_cnt[row_map[(b - 64) * 256 + t]], 1);
        return;
    }
    __shared__ float sred[8];
    const int row = b - 192;
    const size_t i = (size_t)row * DIN + t * 4;
    float4 v = *(const float4*)(X1 + i);
    __half2 hp0 = {__float2half(v.x), __float2half(v.y)};
    __half2 hp1 = {__float2half(v.z), __float2half(v.w)};
    *(__half2*)(g_X1h + i)     = hp0;
    *(__half2*)(g_X1h + i + 2) = hp1;
    const float4 w = *(const float4*)(g_wqbk + t * 4);
    float d = v.x * w.x + v.y * w.y + v.z * w.z + v.w * w.w;
    #pragma unroll
    for (int off = 16; off > 0; off >>= 1) d += __shfl_down_sync(0xFFFFFFFFu, d, off);
    if ((t & 31) == 0) sred[t >> 5] = d;
    __syncthreads();
    if (t < 8) {
        float s = sred[t];
        #pragma unroll
        for (int off = 4; off > 0; off >>= 1) s += __shfl_down_sync(0xFFu, s, off);
        if (t == 0) g_c0[row] = s + g_bqbk[0];
    }
}

// ---------------- scan: 1 block, 256 threads, 16 elems/thread ----------------
__global__ void scan_kernel() {
    __shared__ int wsum[8];
    const int t = threadIdx.x;
    int v[16];
    #pragma unroll
    for (int q = 0; q < 4; q++) {
        int4 c = *(const int4*)&g_cnt[16 * t + 4 * q];
        v[4 * q] = c.x; v[4 * q + 1] = c.y; v[4 * q + 2] = c.z; v[4 * q + 3] = c.w;
    }
    int run = 0;
    #pragma unroll
    for (int i = 0; i < 16; i++) { const int tmp = v[i]; v[i] = run; run += tmp; }
    const int lane = t & 31, w = t >> 5;
    int incl = run;
    #pragma unroll
    for (int off = 1; off < 32; off <<= 1) {
        const int n = __shfl_up_sync(0xFFFFFFFFu, incl, off);
        if (lane >= off) incl += n;
    }
    if (lane == 31) wsum[w] = incl;
    const int lane_excl = incl - run;
    __syncthreads();
    if (t < 8) {
        const int o = wsum[t];
        int s = o;
        #pragma unroll
        for (int off = 1; off < 8; off <<= 1) {
            const int n = __shfl_up_sync(0xFFu, s, off);
            if (t >= off) s += n;
        }
        wsum[t] = s - o;
    }
    __syncthreads();
    const int base = wsum[w] + lane_excl;
    #pragma unroll
    for (int i = 0; i < 16; i++) {
        const int o = base + v[i];
        g_off[16 * t + i] = o;
        g_cur[16 * t + i] = o;
    }
    if (t == 255) g_off[NQ] = base + run;
}

// ---------------- fuseD: U-GEMM (R12 narrow, fp16 out) | fill ------------------
// grid = 256 + 128 blocks x 256, dyn smem GEMM_SMEM
__global__ __launch_bounds__(256, 2)
void fuseD_kernel(const int* __restrict__ row_map)
{
    const int b = blockIdx.x;
    if (b < 256) {                       // U = X1h . G + bq.Wk^T (M=4096,N=1024,K=1024)
        gemm_body<false>(b & 7, b >> 3, g_X1h, nullptr, g_Gh, g_bqWk,
                         nullptr, g_Uh, nullptr, DIN, 1024);
        return;
    }
    const int j = (b - 256) * 256 + threadIdx.x;
    const int pos = atomicAdd(&g_cur[row_map[j]], 1);
    g_idx[pos] = j;
}

// ---------------- C-GEMM: C = Yh . Wv + bv (single-term), empty rows zeroed ----
__global__ __launch_bounds__(256, 2)
void cgemm_kernel(const float* __restrict__ bv, float* __restrict__ out)
{
    gemm_body<false>(blockIdx.x, blockIdx.y, g_Yh, nullptr, g_WvT, bv,
                     out, nullptr, g_cnt, 512, 1024);
}

// ---------------- one-pass attention: per-warp online softmax + reg-resident V --
__global__ void attn_kernel(const float* __restrict__ X2) {
    __shared__ float s_acc[8][DIN];      // 32 KB
    __shared__ float s_m[8], s_den[8];
    const int qi = blockIdx.x;
    const int s = g_off[qi], e = g_off[qi + 1];
    const int t = threadIdx.x, w = t >> 5, lane = t & 31;
    const size_t yo = (size_t)qi * DIN + t * 4;
    if (e == s) {
        __half2 z = {__float2half(0.f), __float2half(0.f)};
        *(__half2*)(g_Yh + yo) = z; *(__half2*)(g_Yh + yo + 2) = z;
        return;
    }
    const float c0 = g_c0[qi];
    // U row (fp16) -> registers
    float uf[32];
    const uint2* uu = (const uint2*)(g_Uh + (size_t)qi * DIN);
    #pragma unroll
    for (int it = 0; it < 8; it++) {
        uint2 p = uu[lane + 32 * it];
        float2 f01 = __half22float2(*(__half2*)&p.x);
        float2 f23 = __half22float2(*(__half2*)&p.y);
        uf[4 * it] = f01.x; uf[4 * it + 1] = f01.y;
        uf[4 * it + 2] = f23.x; uf[4 * it + 3] = f23.y;
    }
    float m = -1e30f, den = 0.f;
    float acc[32];
    #pragma unroll
    for (int i = 0; i < 32; i++) acc[i] = 0.f;

    for (int tt = s + w; tt < e; tt += 8) {
        const int j = g_idx[tt];
        const float4* x4 = (const float4*)(X2 + (size_t)j * DIN);
        float xv[32];
        float d = 0.f;
        #pragma unroll
        for (int it = 0; it < 8; it++) {
            float4 a = x4[lane + 32 * it];
            xv[4 * it] = a.x; xv[4 * it + 1] = a.y;
            xv[4 * it + 2] = a.z; xv[4 * it + 3] = a.w;
            d += a.x * uf[4 * it] + a.y * uf[4 * it + 1]
               + a.z * uf[4 * it + 2] + a.w * uf[4 * it + 3];
        }
        #pragma unroll
        for (int off = 16; off > 0; off >>= 1)
            d += __shfl_xor_sync(0xFFFFFFFFu, d, off);
        const float sc = (d + c0) * 0.044194173824159216f;
        const float mnew = fmaxf(m, sc);
        const float r = expf(m - mnew);
        const float wj = expf(sc - mnew);
        den = den * r + wj;
        #pragma unroll
        for (int i = 0; i < 32; i++) acc[i] = acc[i] * r + wj * xv[i];
        m = mnew;
    }

    if (lane == 0) { s_m[w] = m; s_den[w] = den; }
    #pragma unroll
    for (int it = 0; it < 8; it++) {
        float4 v = make_float4(acc[4 * it], acc[4 * it + 1], acc[4 * it + 2], acc[4 * it + 3]);
        *(float4*)&s_acc[w][4 * (lane + 32 * it)] = v;
    }
    __syncthreads();

    float M = -1e30f;
    #pragma unroll
    for (int ww = 0; ww < 8; ww++) M = fmaxf(M, s_m[ww]);
    float D = 0.f;
    float o0 = 0.f, o1 = 0.f, o2 = 0.f, o3 = 0.f;
    #pragma unroll
    for (int ww = 0; ww < 8; ww++) {
        const float scw = expf(s_m[ww] - M);
        D += s_den[ww] * scw;
        const float4 a = *(const float4*)&s_acc[ww][4 * t];
        o0 += scw * a.x; o1 += scw * a.y; o2 += scw * a.z; o3 += scw * a.w;
    }
    const float inv = 1.0f / D;
    __half2 hp0 = {__float2half(o0 * inv), __float2half(o1 * inv)};
    __half2 hp1 = {__float2half(o2 * inv), __float2half(o3 * inv)};
    *(__half2*)(g_Yh + yo)     = hp0;
    *(__half2*)(g_Yh + yo + 2) = hp1;
}

// ---------------- launcher ----------------
extern "C" void kernel_launch(void* const* d_in, const int* in_sizes, int n_in,
                              void* d_out, int out_size)
{
    const float* X1 = (const float*)d_in[0];
    const float* X2 = (const float*)d_in[1];
    const float* Wq = (const float*)d_in[2];
    const float* bq = (const float*)d_in[3];
    const float* Wk = (const float*)d_in[4];
    const float* bk = (const float*)d_in[5];
    const float* Wv = (const float*)d_in[6];
    const float* bv = (const float*)d_in[7];
    const int*   row_map = (const int*)d_in[8];
    float* out = (float*)d_out;

    cudaFuncSetAttribute(fuseBC_kernel, cudaFuncAttributeMaxDynamicSharedMemorySize, GEMM_SMEM);
    cudaFuncSetAttribute(fuseD_kernel,  cudaFuncAttributeMaxDynamicSharedMemorySize, GEMM_SMEM);
    cudaFuncSetAttribute(cgemm_kernel,  cudaFuncAttributeMaxDynamicSharedMemorySize, GEMM_SMEM);

    // 1. independent prep + zero_cnt
    fuseA_kernel<<<1809, 256>>>(Wq, Wk, Wv, bq, bk);
    // 2. G-GEMM | hist | X1-split + c0
    fuseBC_kernel<<<4288, 256, GEMM_SMEM>>>(row_map, X1);
    // 3. scan (tiny)
    scan_kernel<<<1, 256>>>();
    // 4. U-GEMM (narrow, fp16 out) | fill
    fuseD_kernel<<<384, 256, GEMM_SMEM>>>(row_map);
    // 5. one-pass attention -> Yh (fp16)
    attn_kernel<<<NQ, 256>>>(X2);
    // 6. C = Yh . Wv + bv (single-term), empty rows zeroed
    cgemm_kernel<<<dim3(4, 32), 256, GEMM_SMEM>>>(bv, out);
}

// round 15
// speedup vs baseline: 1.1148x; 1.0196x over previous
#include <cuda_runtime.h>
#include <cuda_fp16.h>
#include <math.h>
#include <stdint.h>

#define NQ 4096
#define NK 32768
#define DIN 1024
#define DQK 512
#define DV 512

// ---------------- scratch (no allocations allowed) ----------------
__device__ __half g_X1h[(size_t)NQ * DIN];
__device__ __half g_Yh[(size_t)NQ * DIN];
__device__ __half g_Uh[(size_t)NQ * DIN];     // U = X1.G + bq.Wk^T (fp16)
__device__ __half g_Wkf[(size_t)DIN * 512];   // fl16(Wk) [d2][c]
__device__ __half g_Wqf[(size_t)DIN * 512];   // fl16(Wq) [d1][c]
__device__ __half g_WvT[(size_t)512 * DIN];   // Wv^T [n][k] fp16
__device__ __half g_Gh[(size_t)DIN * DIN];    // Gt = Wk.Wq^T, fp16
__device__ float g_c0[NQ];                    // Q[i].bk
__device__ float g_bqWk[DIN];
__device__ float g_wqbk[DIN];
__device__ float g_bqbk[1];
__device__ float g_zb[DIN];                   // zero bias (never written)
__device__ int   g_cnt[NQ];
__device__ int   g_off[NQ + 1];
__device__ int   g_cur[NQ];
__device__ int   g_idx[NK];

// ---------------- PTX helpers (portable sm_80+) ----------------
__device__ __forceinline__ void cp16(uint32_t dst, const void* src) {
    asm volatile("cp.async.cg.shared.global [%0], [%1], 16;" :: "r"(dst), "l"(src));
}
__device__ __forceinline__ void cp_commit() {
    asm volatile("cp.async.commit_group;" ::: "memory");
}
template <int N> __device__ __forceinline__ void cp_wait() {
    asm volatile("cp.async.wait_group %0;" :: "n"(N) : "memory");
}
__device__ __forceinline__ void ldsm4(uint32_t* r, uint32_t addr) {
    asm volatile("ldmatrix.sync.aligned.m8n8.x4.shared.b16 {%0,%1,%2,%3}, [%4];"
                 : "=r"(r[0]), "=r"(r[1]), "=r"(r[2]), "=r"(r[3]) : "r"(addr));
}
__device__ __forceinline__ void mma16816(float* c, const uint32_t* a, const uint32_t* b) {
    asm volatile(
        "mma.sync.aligned.m16n8k16.row.col.f32.f16.f16.f32 "
        "{%0,%1,%2,%3}, {%4,%5,%6,%7}, {%8,%9}, {%0,%1,%2,%3};"
        : "+f"(c[0]), "+f"(c[1]), "+f"(c[2]), "+f"(c[3])
        : "r"(a[0]), "r"(a[1]), "r"(a[2]), "r"(a[3]), "r"(b[0]), "r"(b[1]));
}

#define TILE_B   8192
#define GEMM_SMEM 98304     // 2-term: 4 stages x 24KB ; 1-term: 6 stages x 16KB

// ---------------- GEMM body: C = (Ah [+ Al]) * B^T + bias ----------------
// TWO: stage = {Ah, Al, B} x 4 ; !TWO: stage = {A, B} x 6 (same smem footprint)
template <bool TWO>
__device__ __forceinline__ void gemm_body(
    int bx, int by,
    const __half* __restrict__ Ah, const __half* __restrict__ Al,
    const __half* __restrict__ B, const float* __restrict__ bias,
    float* __restrict__ Cf, __half* __restrict__ Ch,
    const int* __restrict__ cnt, int ldc, int kdim)
{
    constexpr int SB_STAGE = (TWO ? 3 : 2) * TILE_B;
    constexpr int NS = TWO ? 4 : 6;
    extern __shared__ char smem[];
    const uint32_t sb = (uint32_t)__cvta_generic_to_shared(smem);
    const int tid = threadIdx.x, wid = tid >> 5, lane = tid & 31;
    const int warp_m = wid & 1, warp_n = wid >> 1;
    const int m_base = by * 128;
    const int n_base = bx * 128;

    float acc[4][4][4];
    #pragma unroll
    for (int i = 0; i < 4; i++)
        #pragma unroll
        for (int j = 0; j < 4; j++)
            #pragma unroll
            for (int k = 0; k < 4; k++) acc[i][j][k] = 0.0f;

    const int fr0 = tid >> 2, fc0 = tid & 3;
    const int fr1 = fr0 + 64;
    const uint32_t fd0 = (uint32_t)(fr0 * 64 + ((fc0 ^ ((fr0 >> 1) & 3)) << 4));
    const uint32_t fd1 = (uint32_t)(fr1 * 64 + ((fc0 ^ ((fr1 >> 1) & 3)) << 4));

    auto issue_loads = [&](int gi) {
        const int koff = gi * 32, s = gi % NS;
        const uint32_t st = sb + s * SB_STAGE;
        const size_t aoff = (size_t)m_base * kdim + koff + fc0 * 8;
        const size_t boff = (size_t)n_base * kdim + koff + fc0 * 8;
        cp16(st + fd0, Ah + aoff + (size_t)fr0 * kdim);
        cp16(st + fd1, Ah + aoff + (size_t)fr1 * kdim);
        if (TWO) {
            cp16(st + TILE_B + fd0, Al + aoff + (size_t)fr0 * kdim);
            cp16(st + TILE_B + fd1, Al + aoff + (size_t)fr1 * kdim);
        }
        const uint32_t sB = st + (TWO ? 2 : 1) * TILE_B;
        cp16(sB + fd0, B + boff + (size_t)fr0 * kdim);
        cp16(sB + fd1, B + boff + (size_t)fr1 * kdim);
        cp_commit();
    };

    const int NSTEP = kdim / 32;
    #pragma unroll
    for (int p = 0; p < NS - 1; p++)
        if (p < NSTEP) issue_loads(p);

    const int a_row = warp_m * 64 + (lane & 15);
    const int a_half = lane >> 4;
    const int a_s = ((lane & 15) >> 1) & 3;
    const int b_row = warp_n * 32 + ((lane >> 4) << 3) + (lane & 7);
    const int b_half = (lane >> 3) & 1;
    const int b_s = ((lane & 7) >> 1) & 3;

    for (int gi = 0; gi < NSTEP; gi++) {
        if (gi + NS - 1 < NSTEP) cp_wait<NS - 2>(); else cp_wait<0>();
        __syncthreads();
        if (gi + NS - 1 < NSTEP) issue_loads(gi + NS - 1);

        const uint32_t st = sb + (gi % NS) * SB_STAGE;
        const uint32_t sAh = st, sAl = st + TILE_B;
        const uint32_t sB = st + (TWO ? 2 : 1) * TILE_B;

        #pragma unroll
        for (int kh = 0; kh < 2; kh++) {
            const uint32_t acb = (uint32_t)(((kh * 2 + a_half) ^ a_s) << 4);
            const uint32_t bcb = (uint32_t)(((kh * 2 + b_half) ^ b_s) << 4);
            uint32_t bf[2][4], af[4][4];
            #pragma unroll
            for (int nf2 = 0; nf2 < 2; nf2++)
                ldsm4(bf[nf2], sB + (uint32_t)((b_row + nf2 * 16) * 64) + bcb);
            #pragma unroll
            for (int mf = 0; mf < 4; mf++)
                ldsm4(af[mf], sAh + (uint32_t)((a_row + mf * 16) * 64) + acb);
            #pragma unroll
            for (int mf = 0; mf < 4; mf++)
                #pragma unroll
                for (int nf = 0; nf < 4; nf++)
                    mma16816(acc[mf][nf], af[mf], &bf[nf >> 1][(nf & 1) * 2]);
            if (TWO) {
                #pragma unroll
                for (int mf = 0; mf < 4; mf++)
                    ldsm4(af[mf], sAl + (uint32_t)((a_row + mf * 16) * 64) + acb);
                #pragma unroll
                for (int mf = 0; mf < 4; mf++)
                    #pragma unroll
                    for (int nf = 0; nf < 4; nf++)
                        mma16816(acc[mf][nf], af[mf], &bf[nf >> 1][(nf & 1) * 2]);
            }
        }
    }

    const int col0 = n_base + warp_n * 32 + (lane & 3) * 2;
    const int r0   = m_base + warp_m * 64 + (lane >> 2);
    #pragma unroll
    for (int mf = 0; mf < 4; mf++) {
        const int ra = r0 + mf * 16, rb = ra + 8;
        const bool za = cnt && (cnt[ra] == 0);
        const bool zbm = cnt && (cnt[rb] == 0);
        #pragma unroll
        for (int nf = 0; nf < 4; nf++) {
            const int col = col0 + nf * 8;
            const float b0 = bias[col], b1 = bias[col + 1];
            float v0 = za ? 0.f : acc[mf][nf][0] + b0;
            float v1 = za ? 0.f : acc[mf][nf][1] + b1;
            float v2 = zbm ? 0.f : acc[mf][nf][2] + b0;
            float v3 = zbm ? 0.f : acc[mf][nf][3] + b1;
            if (Ch) {
                __half2 ha = {__float2half(v0), __float2half(v1)};
                __half2 hb = {__float2half(v2), __float2half(v3)};
                *(__half2*)(Ch + (size_t)ra * ldc + col) = ha;
                *(__half2*)(Ch + (size_t)rb * ldc + col) = hb;
            } else {
                *(float2*)(Cf + (size_t)ra * ldc + col) = make_float2(v0, v1);
                *(float2*)(Cf + (size_t)rb * ldc + col) = make_float2(v2, v3);
            }
        }
    }
}

// ---------------- fuseA: conv-Wk | conv-Wq | wtrans-Wv | zero_cnt | vecprep ----
__global__ void fuseA_kernel(const float* __restrict__ Wq, const float* __restrict__ Wk,
                             const float* __restrict__ Wv, const float* __restrict__ bq,
                             const float* __restrict__ bk)
{
    const int b = blockIdx.x, tid = threadIdx.x;
    if (b < 512) {                       // Wk fp32 -> fp16
        const size_t i = 4 * ((size_t)b * 256 + tid);
        float4 v = *(const float4*)(Wk + i);
        __half2 p0 = {__float2half(v.x), __float2half(v.y)};
        __half2 p1 = {__float2half(v.z), __float2half(v.w)};
        *(__half2*)(g_Wkf + i)     = p0;
        *(__half2*)(g_Wkf + i + 2) = p1;
    } else if (b < 1024) {               // Wq fp32 -> fp16
        const size_t i = 4 * ((size_t)(b - 512) * 256 + tid);
        float4 v = *(const float4*)(Wq + i);
        __half2 p0 = {__float2half(v.x), __float2half(v.y)};
        __half2 p1 = {__float2half(v.z), __float2half(v.w)};
        *(__half2*)(g_Wqf + i)     = p0;
        *(__half2*)(g_Wqf + i + 2) = p1;
    } else if (b < 1536) {               // Wv[k][n] -> WvT[n][k] fp16
        __shared__ float tile[32][33];
        const int bb = b - 1024;
        const int n0 = (bb & 15) * 32, k0 = (bb >> 4) * 32;
        const int tx = tid & 31, ty0 = tid >> 5;
        #pragma unroll
        for (int i = 0; i < 4; i++) {
            const int ty = ty0 + 8 * i;
            tile[ty][tx] = Wv[(size_t)(k0 + ty) * 512 + (n0 + tx)];
        }
        __syncthreads();
        #pragma unroll
        for (int i = 0; i < 4; i++) {
            const int ty = ty0 + 8 * i;
            g_WvT[(size_t)(n0 + ty) * DIN + (k0 + tx)] = __float2half(tile[tx][ty]);
        }
    } else if (b < 1552) {               // zero g_cnt
        g_cnt[(b - 1536) * 256 + tid] = 0;
    } else {                             // vecprep: bqWk, wqbk, bqbk
        const int gw = (b - 1552) * 8 + (tid >> 5);
        const int lane = tid & 31;
        const float* rowp; const float* vecp; float* outp;
        if (gw < DIN)            { rowp = Wk + (size_t)gw * 512;         vecp = bq; outp = g_bqWk + gw; }
        else if (gw < 2 * DIN)   { rowp = Wq + (size_t)(gw - DIN) * 512; vecp = bk; outp = g_wqbk + (gw - DIN); }
        else if (gw == 2 * DIN)  { rowp = bq;                            vecp = bk; outp = g_bqbk; }
        else return;
        const float4* r4 = (const float4*)rowp;
        const float4* v4 = (const float4*)vecp;
        float d = 0.f;
        #pragma unroll
        for (int it = 0; it < 4; it++) {
            float4 a = r4[lane + 32 * it], bb2 = v4[lane + 32 * it];
            d += a.x * bb2.x + a.y * bb2.y + a.z * bb2.z + a.w * bb2.w;
        }
        #pragma unroll
        for (int off = 16; off > 0; off >>= 1) d += __shfl_down_sync(0xFFFFFFFFu, d, off);
        if (lane == 0) *outp = d;
    }
}

// ---------------- fuseBC: G-GEMM (1-term) | hist | X1 split + c0 ---------------
__global__ __launch_bounds__(256, 2)
void fuseBC_kernel(const int* __restrict__ row_map, const float* __restrict__ X1)
{
    const int b = blockIdx.x, t = threadIdx.x;
    if (b < 64) {                        // Gt = fl16(Wk).fl16(Wq)^T (M=1024,N=1024,K=512)
        gemm_body<false>(b & 7, b >> 3, g_Wkf, nullptr, g_Wqf, g_zb,
                         nullptr, g_Gh, nullptr, DIN, 512);
        return;
    }
    if (b < 192) {                       // histogram
        atomicAdd(&g_cnt[row_map[(b - 64) * 256 + t]], 1);
        return;
    }
    __shared__ float sred[8];
    const int row = b - 192;
    const size_t i = (size_t)row * DIN + t * 4;
    float4 v = *(const float4*)(X1 + i);
    __half2 hp0 = {__float2half(v.x), __float2half(v.y)};
    __half2 hp1 = {__float2half(v.z), __float2half(v.w)};
    *(__half2*)(g_X1h + i)     = hp0;
    *(__half2*)(g_X1h + i + 2) = hp1;
    const float4 w = *(const float4*)(g_wqbk + t * 4);
    float d = v.x * w.x + v.y * w.y + v.z * w.z + v.w * w.w;
    #pragma unroll
    for (int off = 16; off > 0; off >>= 1) d += __shfl_down_sync(0xFFFFFFFFu, d, off);
    if ((t & 31) == 0) sred[t >> 5] = d;
    __syncthreads();
    if (t < 8) {
        float s = sred[t];
        #pragma unroll
        for (int off = 4; off > 0; off >>= 1) s += __shfl_down_sync(0xFFu, s, off);
        if (t == 0) g_c0[row] = s + g_bqbk[0];
    }
}

// ---------------- scan: 1 block, 256 threads, 16 elems/thread ----------------
__global__ void scan_kernel() {
    __shared__ int wsum[8];
    const int t = threadIdx.x;
    int v[16];
    #pragma unroll
    for (int q = 0; q < 4; q++) {
        int4 c = *(const int4*)&g_cnt[16 * t + 4 * q];
        v[4 * q] = c.x; v[4 * q + 1] = c.y; v[4 * q + 2] = c.z; v[4 * q + 3] = c.w;
    }
    int run = 0;
    #pragma unroll
    for (int i = 0; i < 16; i++) { const int tmp = v[i]; v[i] = run; run += tmp; }
    const int lane = t & 31, w = t >> 5;
    int incl = run;
    #pragma unroll
    for (int off = 1; off < 32; off <<= 1) {
        const int n = __shfl_up_sync(0xFFFFFFFFu, incl, off);
        if (lane >= off) incl += n;
    }
    if (lane == 31) wsum[w] = incl;
    const int lane_excl = incl - run;
    __syncthreads();
    if (t < 8) {
        const int o = wsum[t];
        int s = o;
        #pragma unroll
        for (int off = 1; off < 8; off <<= 1) {
            const int n = __shfl_up_sync(0xFFu, s, off);
            if (t >= off) s += n;
        }
        wsum[t] = s - o;
    }
    __syncthreads();
    const int base = wsum[w] + lane_excl;
    #pragma unroll
    for (int i = 0; i < 16; i++) {
        const int o = base + v[i];
        g_off[16 * t + i] = o;
        g_cur[16 * t + i] = o;
    }
    if (t == 255) g_off[NQ] = base + run;
}

// ---------------- fuseD: U-GEMM (narrow 1-term, fp16 out) | fill ---------------
__global__ __launch_bounds__(256, 2)
void fuseD_kernel(const int* __restrict__ row_map)
{
    const int b = blockIdx.x;
    if (b < 256) {                       // U = X1h . G + bq.Wk^T (M=4096,N=1024,K=1024)
        gemm_body<false>(b & 7, b >> 3, g_X1h, nullptr, g_Gh, g_bqWk,
                         nullptr, g_Uh, nullptr, DIN, 1024);
        return;
    }
    const int j = (b - 256) * 256 + threadIdx.x;
    const int pos = atomicAdd(&g_cur[row_map[j]], 1);
    g_idx[pos] = j;
}

// ---------------- C-GEMM: C = Yh . Wv + bv (1-term), empty rows zeroed ---------
__global__ __launch_bounds__(256, 2)
void cgemm_kernel(const float* __restrict__ bv, float* __restrict__ out)
{
    gemm_body<false>(blockIdx.x, blockIdx.y, g_Yh, nullptr, g_WvT, bv,
                     out, nullptr, g_cnt, 512, 1024);
}

// ---------------- two-pass attention (R12-proven), fp16 U ---------------------
#define CH 64
__global__ void attn_kernel(const float* __restrict__ X2) {
    __shared__ float ssc[CH];
    const int qi = blockIdx.x;
    const int s = g_off[qi], e = g_off[qi + 1];
    const int t = threadIdx.x, wid = t >> 5, lane = t & 31;
    const size_t yo = (size_t)qi * DIN + t * 4;
    if (e == s) {
        __half2 z = {__float2half(0.f), __float2half(0.f)};
        *(__half2*)(g_Yh + yo) = z; *(__half2*)(g_Yh + yo + 2) = z;
        return;
    }
    const float c0 = g_c0[qi];
    const uint2* uu = (const uint2*)(g_Uh + (size_t)qi * DIN);
    float m = -1e30f, den = 0.f;
    float4 acc = make_float4(0.f, 0.f, 0.f, 0.f);

    for (int t0 = s; t0 < e; t0 += CH) {
        const int nt = min(CH, e - t0);
        for (int tt = wid; tt < nt; tt += 8) {
            const int j = g_idx[t0 + tt];
            const float4* x4 = (const float4*)(X2 + (size_t)j * DIN);
            float d = 0.f;
            #pragma unroll
            for (int it = 0; it < 8; it++) {
                float4 a = x4[lane + 32 * it];
                uint2 p = uu[lane + 32 * it];
                float2 f01 = __half22float2(*(__half2*)&p.x);
                float2 f23 = __half22float2(*(__half2*)&p.y);
                d += a.x * f01.x + a.y * f01.y + a.z * f23.x + a.w * f23.y;
            }
            #pragma unroll
            for (int off = 16; off > 0; off >>= 1)
                d += __shfl_down_sync(0xFFFFFFFFu, d, off);
            if (lane == 0) ssc[tt] = (d + c0) * 0.044194173824159216f;
        }
        __syncthreads();
        float mc = -1e30f;
        for (int k = 0; k < nt; k++) mc = fmaxf(mc, ssc[k]);
        const float mnew = fmaxf(m, mc);
        const float resc = expf(m - mnew);
        den *= resc;
        acc.x *= resc; acc.y *= resc; acc.z *= resc; acc.w *= resc;
        for (int k = 0; k < nt; k++) {
            const int j = g_idx[t0 + k];
            const float w = expf(ssc[k] - mnew);
            den += w;
            const float4 v = *(const float4*)(X2 + (size_t)j * DIN + t * 4);
            acc.x += w * v.x; acc.y += w * v.y; acc.z += w * v.z; acc.w += w * v.w;
        }
        m = mnew;
        __syncthreads();
    }
    const float inv = 1.0f / den;
    __half2 hp0 = {__float2half(acc.x * inv), __float2half(acc.y * inv)};
    __half2 hp1 = {__float2half(acc.z * inv), __float2half(acc.w * inv)};
    *(__half2*)(g_Yh + yo)     = hp0;
    *(__half2*)(g_Yh + yo + 2) = hp1;
}

// ---------------- launcher ----------------
extern "C" void kernel_launch(void* const* d_in, const int* in_sizes, int n_in,
                              void* d_out, int out_size)
{
    const float* X1 = (const float*)d_in[0];
    const float* X2 = (const float*)d_in[1];
    const float* Wq = (const float*)d_in[2];
    const float* bq = (const float*)d_in[3];
    const float* Wk = (const float*)d_in[4];
    const float* bk = (const float*)d_in[5];
    const float* Wv = (const float*)d_in[6];
    const float* bv = (const float*)d_in[7];
    const int*   row_map = (const int*)d_in[8];
    float* out = (float*)d_out;

    cudaFuncSetAttribute(fuseBC_kernel, cudaFuncAttributeMaxDynamicSharedMemorySize, GEMM_SMEM);
    cudaFuncSetAttribute(fuseD_kernel,  cudaFuncAttributeMaxDynamicSharedMemorySize, GEMM_SMEM);
    cudaFuncSetAttribute(cgemm_kernel,  cudaFuncAttributeMaxDynamicSharedMemorySize, GEMM_SMEM);

    // 1. independent prep + zero_cnt
    fuseA_kernel<<<1809, 256>>>(Wq, Wk, Wv, bq, bk);
    // 2. G-GEMM | hist | X1-split + c0
    fuseBC_kernel<<<4288, 256, GEMM_SMEM>>>(row_map, X1);
    // 3. scan (tiny)
    scan_kernel<<<1, 256>>>();
    // 4. U-GEMM (narrow, fp16 out, 6-stage) | fill
    fuseD_kernel<<<384, 256, GEMM_SMEM>>>(row_map);
    // 5. two-pass attention -> Yh (fp16)
    attn_kernel<<<NQ, 256>>>(X2);
    // 6. C = Yh . Wv + bv (1-term, 6-stage), empty rows zeroed
    cgemm_kernel<<<dim3(4, 32), 256, GEMM_SMEM>>>(bv, out);
}